// round 15
// baseline (speedup 1.0000x reference)
#include <cuda_runtime.h>
#include <cstddef>
#include <cstdint>

// Problem constants
#define KCLS 20
#define BB   2
#define TT   12
#define CC   10
#define HWSZ 16384          // 128*128
#define BT   24             // BB*TT
#define FEAT 4097
#define NH   128
#define CHUNK 128
#define NFC  32             // f-chunks of 128 covering 4096; f=4096 folded into bias

// Static device scratch (no allocations allowed)
__device__ float g_part[NFC * KCLS * BT * NH];  // GEMM1 partials, 7.9MB
__device__ float g_A[KCLS * BT * CC];           // 1 + w  coefficient
__device__ float g_Bc[KCLS * BT * CC];           // b      coefficient

__device__ __forceinline__ uint32_t smem_u32(const void* p) {
    uint32_t a;
    asm("{ .reg .u64 t; cvta.to.shared.u64 t, %1; cvt.u32.u64 %0, t; }"
        : "=r"(a) : "l"(p));
    return a;
}

// Packed fp32x2 helpers (Blackwell): one issue slot, two exact fp32 FMAs.
__device__ __forceinline__ unsigned long long ffma2(
    unsigned long long a, unsigned long long b, unsigned long long c) {
    unsigned long long d;
    asm("fma.rn.f32x2 %0, %1, %2, %3;" : "=l"(d) : "l"(a), "l"(b), "l"(c));
    return d;
}
__device__ __forceinline__ unsigned long long pack2(float x, float y) {
    unsigned long long d;
    asm("mov.b64 %0, {%1, %2};" : "=l"(d) : "f"(x), "f"(y));
    return d;
}
__device__ __forceinline__ void unpack2(unsigned long long p, float& x, float& y) {
    asm("mov.b64 {%0, %1}, %2;" : "=f"(x), "=f"(y) : "l"(p));
}

// One paired step: scalar s times weight pair columns (j0,j1) and (j2,j3)
#define PAIRSTEP(SV, U)                                                       \
    {                                                                         \
        unsigned long long sp = pack2((SV), (SV));                            \
        acc2[rr * 2]     = ffma2(sp, w2[U].x, acc2[rr * 2]);                  \
        acc2[rr * 2 + 1] = ffma2(sp, w2[U].y, acc2[rr * 2 + 1]);              \
    }

// Issue one 2KB weight stage (8 features x 64 j) via 1 cp.async.16B per thread.
// Stage layout: [feature f][64 j] ; thread copies f = tid>>4, j = (tid&15)*4.
#define ISSUE_STAGE(SIDX, BUF)                                                \
    {                                                                         \
        uint32_t d = sw_base + (uint32_t)(BUF) * 2048u + (uint32_t)tid * 16u; \
        const float* s = wsrc + (size_t)((SIDX) * 8 + (tid >> 4)) * NH        \
                              + (tid & 15) * 4;                               \
        asm volatile(                                                         \
            "cp.async.cg.shared.global [%0], [%1], 16;\n\t"                   \
            "cp.async.commit_group;"                                          \
            :: "r"(d), "l"(s) : "memory");                                    \
    }

#define DUMMY_COMMIT() asm volatile("cp.async.commit_group;" ::: "memory")
#define WAIT_GROUP2()  asm volatile("cp.async.wait_group 2;" ::: "memory")

// ---------------------------------------------------------------------------
// Kernel 1: GEMM1 partials, j-split for occupancy.
// Block = (fc, k, j-half) -> 1280 blocks x 128 threads.
// 128 threads = 16 j-quads x 8 row-groups (3 rows each).
// W1 streamed via cp.async 4-stage x 2KB smem ring; FFMA2 accumulation.
// Bit-identical g_part (same per-accumulator f-order).
// ---------------------------------------------------------------------------
__global__ __launch_bounds__(128, 6) void gemm1_partial(
    const float* __restrict__ att, const float* __restrict__ W1)
{
    __shared__ __align__(16) float sf[BT * CHUNK];   // 12KB activations
    __shared__ __align__(16) float sw[4 * 512];      // 8KB: 4 weight stages
    const int fc = blockIdx.x, k = blockIdx.y, jh = blockIdx.z;
    const int tid = threadIdx.x;

    const float* wsrc = W1 + ((size_t)k * FEAT + (size_t)fc * CHUNK) * NH + jh * 64;
    const uint32_t sw_base = smem_u32(sw);

    // Prologue: stages 0..2 in flight
    ISSUE_STAGE(0, 0)
    ISSUE_STAGE(1, 1)
    ISSUE_STAGE(2, 2)

    // Activations into smem
    // feat[r, fc*128+q] = att[(fc>>1)*(BT*256) + r*256 + (fc&1)*128 + q]
    const float4* a4 = (const float4*)(att + (size_t)(fc >> 1) * (BT * 256) + (fc & 1) * 128);
    float4* s4 = (float4*)sf;
    #pragma unroll
    for (int i = tid; i < BT * CHUNK / 4; i += 128) {
        int r = i >> 5;          // 32 float4 per row
        int q = i & 31;
        s4[i] = a4[r * 64 + q];  // source row stride = 256 floats
    }
    __syncthreads();

    const int j4 = (tid & 15);   // quad within the 64-column half
    const int rg = tid >> 4;     // row group 0..7 (rows rg*3 .. rg*3+2)

    unsigned long long acc2[6];  // 3 rows x 2 j-pairs, packed f32x2
    #pragma unroll
    for (int i = 0; i < 6; i++) acc2[i] = 0ull;

    const float* sfr = &sf[rg * 3 * CHUNK];

    #pragma unroll 1
    for (int oct = 0; oct < 16; oct++) {
        WAIT_GROUP2();           // stage 'oct' complete (this thread's copy)
        __syncthreads();         // all copies visible; prev buf consumed
        if (oct + 3 < 16) { ISSUE_STAGE(oct + 3, (oct + 3) & 3) }
        else              { DUMMY_COMMIT(); }

        const float* wbuf = &sw[(oct & 3) * 512];
        ulonglong2 w2[8];        // per feature: (w_j0,w_j1),(w_j2,w_j3)
        #pragma unroll
        for (int u = 0; u < 8; u++)
            w2[u] = *(const ulonglong2*)&wbuf[u * 64 + j4 * 4];

        #pragma unroll
        for (int rr = 0; rr < 3; rr++) {
            float4 s0 = *(const float4*)&sfr[rr * CHUNK + oct * 8];
            float4 s1 = *(const float4*)&sfr[rr * CHUNK + oct * 8 + 4];
            PAIRSTEP(s0.x, 0)
            PAIRSTEP(s0.y, 1)
            PAIRSTEP(s0.z, 2)
            PAIRSTEP(s0.w, 3)
            PAIRSTEP(s1.x, 4)
            PAIRSTEP(s1.y, 5)
            PAIRSTEP(s1.z, 6)
            PAIRSTEP(s1.w, 7)
        }
    }

    float* base = g_part + (size_t)((fc * KCLS + k) * BT + rg * 3) * NH + jh * 64;
    ulonglong2* dst = (ulonglong2*)base + j4;
    #pragma unroll
    for (int rr = 0; rr < 3; rr++)
        dst[rr * (NH / 4)] = make_ulonglong2(acc2[rr * 2], acc2[rr * 2 + 1]);
}

// ---------------------------------------------------------------------------
// Kernel 2 (fused): per-(k, row) block: reduce partials + bias + date term
// + relu -> layer2 (+relu) -> layer3 -> emit A, Bc.
// Grid (KCLS, 24) = 480 blocks x 128 threads.
// ---------------------------------------------------------------------------
__global__ __launch_bounds__(128) void mlp_fused_tail(
    const float* __restrict__ W1, const float* __restrict__ b1,
    const float* __restrict__ W2, const float* __restrict__ b2,
    const float* __restrict__ W3, const float* __restrict__ b3,
    const int* __restrict__ bp)
{
    __shared__ float s1[NH];
    __shared__ float s2[NH];
    const int k = blockIdx.x, r = blockIdx.y, j = threadIdx.x;

    // Phase A: h1 for row r (sum 32 partial chunks)
    {
        float s = b1[k * NH + j] + (float)bp[r] * W1[((size_t)k * FEAT + 4096) * NH + j];
        const float* p = g_part + (size_t)(k * BT + r) * NH + j;
        #pragma unroll 8
        for (int fc = 0; fc < NFC; fc++)
            s += p[(size_t)fc * (KCLS * BT * NH)];
        s1[j] = fmaxf(s, 0.f);
    }
    __syncthreads();

    // Phase B: layer 2 (h2 = relu(h1 @ W2 + b2))
    float acc = b2[k * NH + j];
    const float* w2p = W2 + (size_t)k * NH * NH + j;
    for (int i = 0; i < NH; i += 4) {
        float w0 = w2p[(i + 0) * NH];
        float w1_ = w2p[(i + 1) * NH];
        float w2_ = w2p[(i + 2) * NH];
        float w3_ = w2p[(i + 3) * NH];
        float4 s = *(const float4*)&s1[i];
        acc = fmaf(s.x, w0, acc);
        acc = fmaf(s.y, w1_, acc);
        acc = fmaf(s.z, w2_, acc);
        acc = fmaf(s.w, w3_, acc);
    }
    s2[j] = fmaxf(acc, 0.f);
    __syncthreads();

    // Phase C: layer 3 (beta = h2 @ W3 + b3), 20 outputs of 2C
    if (threadIdx.x < 2 * CC) {
        int o = threadIdx.x;
        float a = b3[k * 2 * CC + o];
        const float* w3p = W3 + (size_t)k * NH * (2 * CC) + o;
        #pragma unroll 8
        for (int i = 0; i < NH; i++)
            a = fmaf(s2[i], w3p[i * 2 * CC], a);
        int c = o >> 1;
        if ((o & 1) == 0) g_A [(k * BT + r) * CC + c] = 1.f + a;
        else              g_Bc[(k * BT + r) * CC + c] = a;
    }
}

// ---------------------------------------------------------------------------
// Kernel 3: per-pixel argmin, 2 px/thread, packed f32x2 P/Q accumulation.
//   PQ = sum_t (a_t, b_t) * (x_t, x_t) ; loss'_k = m^2*G1 + m*G2 + G3 - 2*(m*P+Q)
// Grid (HW/256, C, B) x 128 threads, 6 blocks/SM via launch_bounds.
// ---------------------------------------------------------------------------
__global__ __launch_bounds__(128, 6) void classify_kernel(
    const float* __restrict__ input,
    const float* __restrict__ inten,
    float* __restrict__ out)
{
    __shared__ __align__(16) float2 sAB2[KCLS][12]; // (a_t, b_t) pairs
    __shared__ __align__(16) float sG[KCLS][4];     // G1, 2*sum(ab), G3
    const int c = blockIdx.y, b = blockIdx.z, tid = threadIdx.x;

    for (int i = tid; i < KCLS * 12; i += 128) {
        int k = i / 12, t = i % 12;
        sAB2[k][t] = make_float2(g_A [(k * BT + b * TT + t) * CC + c],
                                 g_Bc[(k * BT + b * TT + t) * CC + c]);
    }
    __syncthreads();
    if (tid < KCLS) {
        float g1 = 0.f, g2 = 0.f, g3 = 0.f;
        #pragma unroll
        for (int t = 0; t < TT; t++) {
            float2 ab = sAB2[tid][t];
            g1 = fmaf(ab.x, ab.x, g1);
            g2 = fmaf(ab.x, ab.y, g2);
            g3 = fmaf(ab.y, ab.y, g3);
        }
        sG[tid][0] = g1; sG[tid][1] = 2.f * g2; sG[tid][2] = g3; sG[tid][3] = 0.f;
    }
    __syncthreads();

    const int hw = blockIdx.x * 256 + tid * 2;
    const float* inb = input + (size_t)(b * TT * CC + c) * HWSZ + hw;

    unsigned long long xx0[TT], xx1[TT];
    #pragma unroll
    for (int t = 0; t < TT; t++) {
        float2 v = *(const float2*)(inb + (size_t)t * CC * HWSZ);
        xx0[t] = pack2(v.x, v.x);
        xx1[t] = pack2(v.y, v.y);
    }
    const float2 mm = *(const float2*)(inten + b * HWSZ + hw);
    const float m0 = mm.x, m1 = mm.y;
    const float m20 = m0 * m0, m21 = m1 * m1;

    float best0 = 3.4e38f, best1 = 3.4e38f;
    int k0 = 0, k1 = 0;

    #pragma unroll 2
    for (int k = 0; k < KCLS; k++) {
        unsigned long long PQ0 = 0ull, PQ1 = 0ull;
        #pragma unroll
        for (int th = 0; th < 6; th++) {
            ulonglong2 cc = *(const ulonglong2*)&sAB2[k][th * 2];
            PQ0 = ffma2(cc.x, xx0[th * 2    ], PQ0);
            PQ0 = ffma2(cc.y, xx0[th * 2 + 1], PQ0);
            PQ1 = ffma2(cc.x, xx1[th * 2    ], PQ1);
            PQ1 = ffma2(cc.y, xx1[th * 2 + 1], PQ1);
        }
        float P0, Q0, P1, Q1;
        unpack2(PQ0, P0, Q0);
        unpack2(PQ1, P1, Q1);
        const float4 g = *(const float4*)&sG[k][0];
        float l, r;
        l = fmaf(m20, g.x, fmaf(m0, g.y, g.z)); r = fmaf(m0, P0, Q0); l = fmaf(r, -2.f, l);
        if (l < best0) { best0 = l; k0 = k; }
        l = fmaf(m21, g.x, fmaf(m1, g.y, g.z)); r = fmaf(m1, P1, Q1); l = fmaf(r, -2.f, l);
        if (l < best1) { best1 = l; k1 = k; }
    }

    float* ob = out + (size_t)(b * TT * CC + c) * HWSZ + hw;
    #pragma unroll
    for (int t = 0; t < TT; t++) {
        float2 p0 = sAB2[k0][t];
        float2 p1 = sAB2[k1][t];
        float2 o;
        o.x = fmaf(p0.x, m0, p0.y);
        o.y = fmaf(p1.x, m1, p1.y);
        *(float2*)(ob + (size_t)t * CC * HWSZ) = o;
    }

    // intensity_map tail (second tuple element), written once (c==0 blocks)
    if (blockIdx.y == 0) {
        float* tail = out + (size_t)BB * TT * CC * HWSZ + b * HWSZ + hw;
        *(float2*)tail = mm;
    }
}

// ---------------------------------------------------------------------------
// Launch. Inputs: input, batch_positions(int32), intensity_map, att,
// W1, b1, W2, b2, W3, b3. Output: concat(output[B,T,C,H,W], intensity_map).
// ---------------------------------------------------------------------------
extern "C" void kernel_launch(void* const* d_in, const int* in_sizes, int n_in,
                              void* d_out, int out_size)
{
    const float* input = (const float*)d_in[0];
    const int*   bp    = (const int*)  d_in[1];
    const float* inten = (const float*)d_in[2];
    const float* att   = (const float*)d_in[3];
    const float* W1    = (const float*)d_in[4];
    const float* b1    = (const float*)d_in[5];
    const float* W2    = (const float*)d_in[6];
    const float* b2    = (const float*)d_in[7];
    const float* W3    = (const float*)d_in[8];
    const float* b3    = (const float*)d_in[9];
    float* out = (float*)d_out;

    gemm1_partial<<<dim3(NFC, KCLS, 2), 128>>>(att, W1);
    mlp_fused_tail<<<dim3(KCLS, BT), 128>>>(W1, b1, W2, b2, W3, b3, bp);
    classify_kernel<<<dim3(HWSZ / 256, CC, BB), 128>>>(input, inten, out);
}

// round 17
// speedup vs baseline: 1.0854x; 1.0854x over previous
#include <cuda_runtime.h>
#include <cstddef>
#include <cstdint>

// Problem constants
#define KCLS 20
#define BB   2
#define TT   12
#define CC   10
#define HWSZ 16384          // 128*128
#define BT   24             // BB*TT
#define FEAT 4097
#define NH   128
#define CHUNK 128
#define NFC  32             // f-chunks of 128 covering 4096; f=4096 folded into bias

// Static device scratch (no allocations allowed)
__device__ float g_part[NFC * KCLS * BT * NH];  // GEMM1 partials, 7.9MB
__device__ float g_A[KCLS * BT * CC];           // 1 + w  coefficient
__device__ float g_Bc[KCLS * BT * CC];          // b      coefficient

__device__ __forceinline__ uint32_t smem_u32(const void* p) {
    uint32_t a;
    asm("{ .reg .u64 t; cvta.to.shared.u64 t, %1; cvt.u32.u64 %0, t; }"
        : "=r"(a) : "l"(p));
    return a;
}

// Packed fp32x2 helpers (Blackwell): one issue slot, two exact fp32 FMAs.
__device__ __forceinline__ unsigned long long ffma2(
    unsigned long long a, unsigned long long b, unsigned long long c) {
    unsigned long long d;
    asm("fma.rn.f32x2 %0, %1, %2, %3;" : "=l"(d) : "l"(a), "l"(b), "l"(c));
    return d;
}
__device__ __forceinline__ unsigned long long pack2(float x, float y) {
    unsigned long long d;
    asm("mov.b64 %0, {%1, %2};" : "=l"(d) : "f"(x), "f"(y));
    return d;
}
__device__ __forceinline__ void unpack2(unsigned long long p, float& x, float& y) {
    asm("mov.b64 {%0, %1}, %2;" : "=f"(x), "=f"(y) : "l"(p));
}

// One paired step: scalar s times weight pair columns (j0,j1) and (j2,j3)
#define PAIRSTEP(SV, U)                                                       \
    {                                                                         \
        unsigned long long sp = pack2((SV), (SV));                            \
        acc2[rr * 2]     = ffma2(sp, w2[U].x, acc2[rr * 2]);                  \
        acc2[rr * 2 + 1] = ffma2(sp, w2[U].y, acc2[rr * 2 + 1]);              \
    }

// FMA octave from weight regs w2[8] at feature offset FOFF (8 features)
#define OCTAVE_FMA2(FOFF)                                                     \
    _Pragma("unroll")                                                         \
    for (int rr = 0; rr < 6; rr++) {                                          \
        float4 s0 = *(const float4*)&sfr[rr * CHUNK + (FOFF)];                \
        float4 s1 = *(const float4*)&sfr[rr * CHUNK + (FOFF) + 4];            \
        PAIRSTEP(s0.x, 0)                                                     \
        PAIRSTEP(s0.y, 1)                                                     \
        PAIRSTEP(s0.z, 2)                                                     \
        PAIRSTEP(s0.w, 3)                                                     \
        PAIRSTEP(s1.x, 4)                                                     \
        PAIRSTEP(s1.y, 5)                                                     \
        PAIRSTEP(s1.z, 6)                                                     \
        PAIRSTEP(s1.w, 7)                                                     \
    }

// Issue one 8KB weight stage (16 features x 128 j) via 4 cp.async.16B/thread.
// Each instruction: warp covers a contiguous 512B global segment.
#define ISSUE_STAGE16(SIDX, BUF)                                              \
    {                                                                         \
        uint32_t d = sw_base + (uint32_t)(BUF) * 8192u + (uint32_t)tid * 16u; \
        const float* s = wsrc + (size_t)(SIDX) * 2048 + tid * 4;              \
        asm volatile(                                                         \
            "cp.async.cg.shared.global [%0], [%1], 16;\n\t"                   \
            "cp.async.cg.shared.global [%2], [%3], 16;\n\t"                   \
            "cp.async.cg.shared.global [%4], [%5], 16;\n\t"                   \
            "cp.async.cg.shared.global [%6], [%7], 16;\n\t"                   \
            "cp.async.commit_group;"                                          \
            :: "r"(d),         "l"(s),                                        \
               "r"(d + 2048u), "l"(s + 512),                                  \
               "r"(d + 4096u), "l"(s + 1024),                                 \
               "r"(d + 6144u), "l"(s + 1536) : "memory");                     \
    }

#define DUMMY_COMMIT() asm volatile("cp.async.commit_group;" ::: "memory")
#define WAIT_GROUP1()  asm volatile("cp.async.wait_group 1;" ::: "memory")

// ---------------------------------------------------------------------------
// Kernel 1: GEMM1 partials (R14 tile shape; 2 octaves per sync).
// W1 via cp.async 3-stage x 8KB smem ring; FFMA2 accumulation.
// Block = (fc, k), 640 blocks x 128 threads = 32 j-quads x 4 row-groups.
// Bit-identical g_part (same per-accumulator f-order).
// ---------------------------------------------------------------------------
__global__ __launch_bounds__(128, 5) void gemm1_partial(
    const float* __restrict__ att, const float* __restrict__ W1)
{
    __shared__ __align__(16) float sf[BT * CHUNK];   // 12KB activations
    __shared__ __align__(16) float sw[3 * 2048];     // 24KB: 3 x 8KB stages
    const int fc = blockIdx.x, k = blockIdx.y, tid = threadIdx.x;

    const float* wsrc = W1 + ((size_t)k * FEAT + (size_t)fc * CHUNK) * NH;
    const uint32_t sw_base = smem_u32(sw);

    // Prologue: stages 0..1 in flight (16KB)
    ISSUE_STAGE16(0, 0)
    ISSUE_STAGE16(1, 1)

    // Activations into smem
    // feat[r, fc*128+q] = att[(fc>>1)*(BT*256) + r*256 + (fc&1)*128 + q]
    const float4* a4 = (const float4*)(att + (size_t)(fc >> 1) * (BT * 256) + (fc & 1) * 128);
    float4* s4 = (float4*)sf;
    #pragma unroll
    for (int i = tid; i < BT * CHUNK / 4; i += 128) {
        int r = i >> 5;          // 32 float4 per row
        int q = i & 31;
        s4[i] = a4[r * 64 + q];  // source row stride = 256 floats
    }
    __syncthreads();

    const int j4 = (tid & 31);   // float4 index into j
    const int rg = tid >> 5;     // row group 0..3 (rows rg*6 .. rg*6+5)

    unsigned long long acc2[12]; // 6 rows x 2 j-pairs, packed f32x2
    #pragma unroll
    for (int i = 0; i < 12; i++) acc2[i] = 0ull;

    const float* sfr = &sf[rg * 6 * CHUNK];

    int buf = 0, nbuf = 2;       // current stage buffer / buffer to fill next
    #pragma unroll 1
    for (int step = 0; step < 8; step++) {   // 16 features per step
        WAIT_GROUP1();           // stage 'step' complete (this thread's copies)
        __syncthreads();         // all copies visible; oldest buf consumed
        if (step + 2 < 8) { ISSUE_STAGE16(step + 2, nbuf) }
        else              { DUMMY_COMMIT(); }

        const float* wbuf = &sw[buf * 2048];
        {
            ulonglong2 w2[8];
            #pragma unroll
            for (int u = 0; u < 8; u++)
                w2[u] = *(const ulonglong2*)&wbuf[u * NH + j4 * 4];
            OCTAVE_FMA2(step * 16)
        }
        {
            ulonglong2 w2[8];
            #pragma unroll
            for (int u = 0; u < 8; u++)
                w2[u] = *(const ulonglong2*)&wbuf[(8 + u) * NH + j4 * 4];
            OCTAVE_FMA2(step * 16 + 8)
        }

        if (++buf == 3) buf = 0;
        if (++nbuf == 3) nbuf = 0;
    }

    ulonglong2* dst = (ulonglong2*)(g_part + (size_t)((fc * KCLS + k) * BT + rg * 6) * NH) + j4;
    #pragma unroll
    for (int rr = 0; rr < 6; rr++)
        dst[rr * (NH / 4)] = make_ulonglong2(acc2[rr * 2], acc2[rr * 2 + 1]);
}

// ---------------------------------------------------------------------------
// Kernel 2 (fused): per-(k, row) block: reduce partials + bias + date term
// + relu -> layer2 (+relu) -> layer3 -> emit A, Bc.
// Grid (KCLS, 24) = 480 blocks x 128 threads.
// ---------------------------------------------------------------------------
__global__ __launch_bounds__(128) void mlp_fused_tail(
    const float* __restrict__ W1, const float* __restrict__ b1,
    const float* __restrict__ W2, const float* __restrict__ b2,
    const float* __restrict__ W3, const float* __restrict__ b3,
    const int* __restrict__ bp)
{
    __shared__ float s1[NH];
    __shared__ float s2[NH];
    const int k = blockIdx.x, r = blockIdx.y, j = threadIdx.x;

    // Phase A: h1 for row r (sum 32 partial chunks)
    {
        float s = b1[k * NH + j] + (float)bp[r] * W1[((size_t)k * FEAT + 4096) * NH + j];
        const float* p = g_part + (size_t)(k * BT + r) * NH + j;
        #pragma unroll 8
        for (int fc = 0; fc < NFC; fc++)
            s += p[(size_t)fc * (KCLS * BT * NH)];
        s1[j] = fmaxf(s, 0.f);
    }
    __syncthreads();

    // Phase B: layer 2 (h2 = relu(h1 @ W2 + b2))
    float acc = b2[k * NH + j];
    const float* w2p = W2 + (size_t)k * NH * NH + j;
    for (int i = 0; i < NH; i += 4) {
        float w0 = w2p[(i + 0) * NH];
        float w1_ = w2p[(i + 1) * NH];
        float w2_ = w2p[(i + 2) * NH];
        float w3_ = w2p[(i + 3) * NH];
        float4 s = *(const float4*)&s1[i];
        acc = fmaf(s.x, w0, acc);
        acc = fmaf(s.y, w1_, acc);
        acc = fmaf(s.z, w2_, acc);
        acc = fmaf(s.w, w3_, acc);
    }
    s2[j] = fmaxf(acc, 0.f);
    __syncthreads();

    // Phase C: layer 3 (beta = h2 @ W3 + b3), 20 outputs of 2C
    if (threadIdx.x < 2 * CC) {
        int o = threadIdx.x;
        float a = b3[k * 2 * CC + o];
        const float* w3p = W3 + (size_t)k * NH * (2 * CC) + o;
        #pragma unroll 8
        for (int i = 0; i < NH; i++)
            a = fmaf(s2[i], w3p[i * 2 * CC], a);
        int c = o >> 1;
        if ((o & 1) == 0) g_A [(k * BT + r) * CC + c] = 1.f + a;
        else              g_Bc[(k * BT + r) * CC + c] = a;
    }
}

// ---------------------------------------------------------------------------
// Kernel 3: per-pixel argmin, 2 px/thread, packed f32x2 P/Q accumulation.
//   PQ = sum_t (a_t, b_t) * (x_t, x_t) ; loss'_k = m^2*G1 + m*G2 + G3 - 2*(m*P+Q)
// Grid (HW/256, C, B) x 128 threads, 6 blocks/SM via launch_bounds.
// ---------------------------------------------------------------------------
__global__ __launch_bounds__(128, 6) void classify_kernel(
    const float* __restrict__ input,
    const float* __restrict__ inten,
    float* __restrict__ out)
{
    __shared__ __align__(16) float2 sAB2[KCLS][12]; // (a_t, b_t) pairs
    __shared__ __align__(16) float sG[KCLS][4];     // G1, 2*sum(ab), G3
    const int c = blockIdx.y, b = blockIdx.z, tid = threadIdx.x;

    for (int i = tid; i < KCLS * 12; i += 128) {
        int k = i / 12, t = i % 12;
        sAB2[k][t] = make_float2(g_A [(k * BT + b * TT + t) * CC + c],
                                 g_Bc[(k * BT + b * TT + t) * CC + c]);
    }
    __syncthreads();
    if (tid < KCLS) {
        float g1 = 0.f, g2 = 0.f, g3 = 0.f;
        #pragma unroll
        for (int t = 0; t < TT; t++) {
            float2 ab = sAB2[tid][t];
            g1 = fmaf(ab.x, ab.x, g1);
            g2 = fmaf(ab.x, ab.y, g2);
            g3 = fmaf(ab.y, ab.y, g3);
        }
        sG[tid][0] = g1; sG[tid][1] = 2.f * g2; sG[tid][2] = g3; sG[tid][3] = 0.f;
    }
    __syncthreads();

    const int hw = blockIdx.x * 256 + tid * 2;
    const float* inb = input + (size_t)(b * TT * CC + c) * HWSZ + hw;

    unsigned long long xx0[TT], xx1[TT];
    #pragma unroll
    for (int t = 0; t < TT; t++) {
        float2 v = *(const float2*)(inb + (size_t)t * CC * HWSZ);
        xx0[t] = pack2(v.x, v.x);
        xx1[t] = pack2(v.y, v.y);
    }
    const float2 mm = *(const float2*)(inten + b * HWSZ + hw);
    const float m0 = mm.x, m1 = mm.y;
    const float m20 = m0 * m0, m21 = m1 * m1;

    float best0 = 3.4e38f, best1 = 3.4e38f;
    int k0 = 0, k1 = 0;

    #pragma unroll 2
    for (int k = 0; k < KCLS; k++) {
        unsigned long long PQ0 = 0ull, PQ1 = 0ull;
        #pragma unroll
        for (int th = 0; th < 6; th++) {
            ulonglong2 cc = *(const ulonglong2*)&sAB2[k][th * 2];
            PQ0 = ffma2(cc.x, xx0[th * 2    ], PQ0);
            PQ0 = ffma2(cc.y, xx0[th * 2 + 1], PQ0);
            PQ1 = ffma2(cc.x, xx1[th * 2    ], PQ1);
            PQ1 = ffma2(cc.y, xx1[th * 2 + 1], PQ1);
        }
        float P0, Q0, P1, Q1;
        unpack2(PQ0, P0, Q0);
        unpack2(PQ1, P1, Q1);
        const float4 g = *(const float4*)&sG[k][0];
        float l, r;
        l = fmaf(m20, g.x, fmaf(m0, g.y, g.z)); r = fmaf(m0, P0, Q0); l = fmaf(r, -2.f, l);
        if (l < best0) { best0 = l; k0 = k; }
        l = fmaf(m21, g.x, fmaf(m1, g.y, g.z)); r = fmaf(m1, P1, Q1); l = fmaf(r, -2.f, l);
        if (l < best1) { best1 = l; k1 = k; }
    }

    float* ob = out + (size_t)(b * TT * CC + c) * HWSZ + hw;
    #pragma unroll
    for (int t = 0; t < TT; t++) {
        float2 p0 = sAB2[k0][t];
        float2 p1 = sAB2[k1][t];
        float2 o;
        o.x = fmaf(p0.x, m0, p0.y);
        o.y = fmaf(p1.x, m1, p1.y);
        *(float2*)(ob + (size_t)t * CC * HWSZ) = o;
    }

    // intensity_map tail (second tuple element), written once (c==0 blocks)
    if (blockIdx.y == 0) {
        float* tail = out + (size_t)BB * TT * CC * HWSZ + b * HWSZ + hw;
        *(float2*)tail = mm;
    }
}

// ---------------------------------------------------------------------------
// Launch. Inputs: input, batch_positions(int32), intensity_map, att,
// W1, b1, W2, b2, W3, b3. Output: concat(output[B,T,C,H,W], intensity_map).
// ---------------------------------------------------------------------------
extern "C" void kernel_launch(void* const* d_in, const int* in_sizes, int n_in,
                              void* d_out, int out_size)
{
    const float* input = (const float*)d_in[0];
    const int*   bp    = (const int*)  d_in[1];
    const float* inten = (const float*)d_in[2];
    const float* att   = (const float*)d_in[3];
    const float* W1    = (const float*)d_in[4];
    const float* b1    = (const float*)d_in[5];
    const float* W2    = (const float*)d_in[6];
    const float* b2    = (const float*)d_in[7];
    const float* W3    = (const float*)d_in[8];
    const float* b3    = (const float*)d_in[9];
    float* out = (float*)d_out;

    gemm1_partial<<<dim3(NFC, KCLS), 128>>>(att, W1);
    mlp_fused_tail<<<dim3(KCLS, BT), 128>>>(W1, b1, W2, b2, W3, b3, bp);
    classify_kernel<<<dim3(HWSZ / 256, CC, BB), 128>>>(input, inten, out);
}